// round 10
// baseline (speedup 1.0000x reference)
#include <cuda_runtime.h>

#define HALFW 6
#define MAXC  63
#define NK    21
#define NB    64
#define NC    256
#define NH    64
#define NW    64
#define HW    (NH * NW)
#define STRIP 8                   // rows per block
#define XB    (NH / STRIP)        // 8 strips per image
#define NBLK  (XB * NB * 2)       // 1024 blocks
#define FULLM 0xffffffffu

// Scratch (allocation-free rule: __device__ globals; zero-initialized)
__device__ float g_part[2][NB][XB][NK];   // per-strip raw box partial sums
__device__ int   g_done = 0;              // grid completion (self-resetting)

// ---------------------------------------------------------------------------
// Single fused kernel. grid = (8, 64, 2), block = 128 (4 warps).
// R8 structure verbatim, on 8-row strips: ~7 blocks resident/SM stagger so
// prologues/epilogues overlap other blocks' streaming.
//  - warp0 builds a 16-bit mask of needed 128B lines (8 rows x 2 half-rows)
//  - 128 threads = 16 line slots x 8 float4s -> channel-reduce needed lines
//  - strip fm staged in smem; 21 per-strip box partials -> g_part
//  - last of 1024 blocks reduces g_part + computes MSE
// ---------------------------------------------------------------------------
__global__ void __launch_bounds__(128) fused_kernel(
    const float* __restrict__ f1, const float* __restrict__ f2,
    const int* __restrict__ pre1, const int* __restrict__ pre2,
    float* __restrict__ out)
{
    const int t   = blockIdx.z;
    const int b   = blockIdx.y;
    const int tid = threadIdx.x;
    const int h0  = blockIdx.x * STRIP;       // this block's row base

    __shared__ __align__(16) float s_fm[STRIP * NW];   // strip chan-means, 2KB
    __shared__ int      s_pre[2 * NK];
    __shared__ unsigned s_mask;

    const int* __restrict__ pre = (t == 0) ? pre1 : pre2;
    if (tid < 2 * NK) s_pre[tid] = pre[b * 2 * NK + tid];
    __syncthreads();

    // ---- needed-line mask: line L = (row h0+(L>>1), half (L&1)), L<16 ----
    if (tid < 32) {
        const int h  = h0 + (tid >> 1);
        const int c0 = (tid & 1) * 32;        // half-row col base
        bool need = false;
        if (tid < 2 * STRIP) {
#pragma unroll
            for (int k = 0; k < NK; ++k) {
                const int x = s_pre[2 * k + 0];
                const int y = s_pre[2 * k + 1];
                const int left  = max(x - HALFW, 0);
                const int right = min(x + HALFW, MAXC);   // exclusive
                const int down  = max(y - HALFW, 0);
                const int up    = min(y + HALFW, MAXC);   // exclusive
                need |= (h >= left) & (h < right) & (down < c0 + 32) & (up > c0);
            }
        }
        const unsigned m = __ballot_sync(FULLM, need);
        if (tid == 0) s_mask = m;
    }
    __syncthreads();

    const unsigned mask = s_mask;
    const int nlines    = __popc(mask);
    const int j         = tid >> 3;           // line slot 0..15
    const int f         = tid & 7;            // float4 within 128B line

    // ---- channel reduce over needed lines only (proven loop shape) ----
    if (j < nlines) {
        const int line = __fns(mask, 0, j + 1);   // (j+1)-th set bit
        const int lr = line >> 1;
        const int c4 = (line & 1) * 8 + f;        // float4 col 0..15
        const int hw4 = (h0 + lr) * 16 + c4;

        const float4* __restrict__ f4 =
            reinterpret_cast<const float4*>(t == 0 ? f1 : f2);
        const float4* __restrict__ p = f4 + (size_t)b * NC * (HW / 4) + hw4;

        float4 acc = make_float4(0.f, 0.f, 0.f, 0.f);
#pragma unroll 8
        for (int c = 0; c < NC; ++c) {
            float4 v = p[(size_t)c * (HW / 4)];
            acc.x += v.x; acc.y += v.y; acc.z += v.z; acc.w += v.w;
        }
        const float sc = 1.0f / (float)NC;
        float4 o = make_float4(acc.x * sc, acc.y * sc, acc.z * sc, acc.w * sc);
        *reinterpret_cast<float4*>(&s_fm[lr * NW + c4 * 4]) = o;
    }
    __syncthreads();

    // ---- per-strip box partials: warp-per-keypoint, div-free 12x12 ----
    const int warp = tid >> 5;
    const int lane = tid & 31;
    for (int k = warp; k < NK; k += 4) {
        const int x = s_pre[2 * k + 0];
        const int y = s_pre[2 * k + 1];
        const int left  = max(x - HALFW, 0);
        const int right = min(x + HALFW, MAXC);
        const int down  = max(y - HALFW, 0);
        const int up    = min(y + HALFW, MAXC);
        const int rl = max(left, h0);
        const int rr = min(right, h0 + STRIP);
        const int nhl = rr - rl;              // may be <= 0
        const int nw  = up - down;            // 6..12

        float s = 0.f;
#pragma unroll
        for (int it = 0; it < 3; ++it) {
            const int idx = lane + 32 * it;   // 0..95 (strip box <= 8x12=96)
            const int r = idx / 12;           // constant divisor -> mul/shift
            const int c = idx - r * 12;
            if ((r < nhl) && (c < nw))
                s += s_fm[(rl - h0 + r) * NW + (down + c)];
        }
#pragma unroll
        for (int off = 16; off > 0; off >>= 1)
            s += __shfl_down_sync(FULLM, s, off);
        if (lane == 0)
            g_part[t][b][blockIdx.x][k] = s;  // every slot written each call
    }

    // ---- grid completion: last of 1024 blocks finishes ----
    __shared__ int s_last;
    __threadfence();
    __syncthreads();
    if (tid == 0)
        s_last = (atomicAdd(&g_done, 1) == NBLK - 1) ? 1 : 0;
    __syncthreads();
    if (!s_last) return;

    __threadfence();
    __shared__ float s_fea[2 * NK];
    for (int g = warp; g < 2 * NK; g += 4) {
        const int tt = g / NK;
        const int kk = g - tt * NK;
        const int* __restrict__ pp = (tt == 0) ? pre1 : pre2;
        float v = 0.f;
#pragma unroll
        for (int half = 0; half < 2; ++half) {
            const int bb = lane + 32 * half;
            const int x = pp[(bb * NK + kk) * 2 + 0];
            const int y = pp[(bb * NK + kk) * 2 + 1];
            const int cnt = (min(x + HALFW, MAXC) - max(x - HALFW, 0)) *
                            (min(y + HALFW, MAXC) - max(y - HALFW, 0));
            float ssum = 0.f;
#pragma unroll
            for (int xb = 0; xb < XB; ++xb)
                ssum += __ldcg(&g_part[tt][bb][xb][kk]);
            v += ssum * (1.0f / (float)cnt);
        }
#pragma unroll
        for (int off = 16; off > 0; off >>= 1)
            v += __shfl_down_sync(FULLM, v, off);
        if (lane == 0)
            s_fea[g] = v * (1.0f / (float)NB);
    }
    __syncthreads();
    if (tid == 0) {
        float acc2 = 0.f;
#pragma unroll
        for (int kk = 0; kk < NK; ++kk) {
            const float d = s_fea[kk] - 0.999f * s_fea[NK + kk];
            acc2 += d * d;
        }
        out[0] = acc2 * (1.0f / (float)NK);
        g_done = 0;                           // reset for next replay
    }
}

extern "C" void kernel_launch(void* const* d_in, const int* in_sizes, int n_in,
                              void* d_out, int out_size)
{
    const float* f1   = (const float*)d_in[0];
    const float* f2   = (const float*)d_in[1];
    const int*   pre1 = (const int*)d_in[2];
    const int*   pre2 = (const int*)d_in[3];

    fused_kernel<<<dim3(XB, NB, 2), 128>>>(f1, f2, pre1, pre2, (float*)d_out);
}

// round 11
// speedup vs baseline: 1.0281x; 1.0281x over previous
#include <cuda_runtime.h>

#define HALFW 6
#define MAXC  63
#define NK    21
#define NB    64
#define NC    256
#define NH    64
#define NW    64
#define HW    (NH * NW)
#define NBLK  512                 // (4, 64, 2)
#define FULLM 0xffffffffu

// Scratch (allocation-free rule: __device__ globals; zero-initialized)
__device__ float g_part[2][NB][4][NK];  // per-strip raw box partial sums
__device__ int   g_done = 0;            // grid completion (self-resetting)

// ---------------------------------------------------------------------------
// Single fused kernel. grid = (4, 64, 2), block = 256.
//  - DENSE stream, bit-identical mapping to the proven 80.4us/85%-DRAM loop
//  - zero barriers before the first LDG (s_pre written pre-stream, read after
//    the single post-stream __syncthreads)
//  - fm tile staged in smem (no global g_fm); per-block clipped box partials
//    (warp-per-keypoint, div-free 12x12) -> 21 floats to g_part
//  - last of 512 blocks reduces g_part + computes the MSE
// ---------------------------------------------------------------------------
__global__ void __launch_bounds__(256) fused_kernel(
    const float* __restrict__ f1, const float* __restrict__ f2,
    const int* __restrict__ pre1, const int* __restrict__ pre2,
    float* __restrict__ out)
{
    const int t   = blockIdx.z;
    const int b   = blockIdx.y;
    const int tid = threadIdx.x;
    const int h0  = blockIdx.x * 16;          // this block's row base

    __shared__ __align__(16) float s_fm[16 * NW];  // fm tile (chan-mean), 4KB
    __shared__ int s_pre[2 * NK];

    // no barrier here: s_pre is only read after the post-stream syncthreads
    const int* __restrict__ pre = (t == 0) ? pre1 : pre2;
    if (tid < 2 * NK) s_pre[tid] = pre[b * 2 * NK + tid];

    // ---- dense channel reduce: PROVEN loop, unchanged mapping ----
    {
        const int hw4 = blockIdx.x * 256 + tid;        // 0..1023
        const float4* __restrict__ f4 =
            reinterpret_cast<const float4*>(t == 0 ? f1 : f2);
        const float4* __restrict__ p = f4 + (size_t)b * NC * (HW / 4) + hw4;

        float4 acc = make_float4(0.f, 0.f, 0.f, 0.f);
#pragma unroll 8
        for (int c = 0; c < NC; ++c) {
            float4 v = p[(size_t)c * (HW / 4)];
            acc.x += v.x; acc.y += v.y; acc.z += v.z; acc.w += v.w;
        }
        const float sc = 1.0f / (float)NC;
        float4 o = make_float4(acc.x * sc, acc.y * sc, acc.z * sc, acc.w * sc);
        // tid = local row (tid>>4) * 16 float4-cols + (tid&15)
        *reinterpret_cast<float4*>(&s_fm[(tid >> 4) * NW + (tid & 15) * 4]) = o;
    }
    __syncthreads();                          // s_fm + s_pre both ready

    // ---- per-block box partials: warp-per-keypoint, div-free 12x12 ----
    const int warp = tid >> 5;
    const int lane = tid & 31;
    for (int k = warp; k < NK; k += 8) {
        const int x = s_pre[2 * k + 0];
        const int y = s_pre[2 * k + 1];
        // x masks rows (H), y masks cols (W); exclusive upper bounds.
        const int left  = max(x - HALFW, 0);
        const int right = min(x + HALFW, MAXC);
        const int down  = max(y - HALFW, 0);
        const int up    = min(y + HALFW, MAXC);
        const int rl = max(left, h0);
        const int rr = min(right, h0 + 16);
        const int nhl = rr - rl;              // may be <= 0
        const int nw  = up - down;            // 6..12

        float s = 0.f;
#pragma unroll
        for (int it = 0; it < 5; ++it) {
            const int idx = lane + 32 * it;   // 0..159
            const int r = idx / 12;           // constant divisor -> mul/shift
            const int c = idx - r * 12;
            if ((idx < 144) && (r < nhl) && (c < nw))
                s += s_fm[(rl - h0 + r) * NW + (down + c)];
        }
#pragma unroll
        for (int off = 16; off > 0; off >>= 1)
            s += __shfl_down_sync(FULLM, s, off);
        if (lane == 0)
            g_part[t][b][blockIdx.x][k] = s;  // every slot written each call
    }

    // ---- grid completion: last of 512 blocks finishes ----
    __shared__ int s_last;
    if (lane == 0) __threadfence();           // order this warp's g_part store
    __syncthreads();
    if (tid == 0)
        s_last = (atomicAdd(&g_done, 1) == NBLK - 1) ? 1 : 0;
    __syncthreads();
    if (!s_last) return;

    __threadfence();
    __shared__ float s_fea[2 * NK];
    for (int g = warp; g < 2 * NK; g += 8) {
        const int tt = g / NK;
        const int kk = g - tt * NK;
        const int* __restrict__ pp = (tt == 0) ? pre1 : pre2;
        float v = 0.f;
#pragma unroll
        for (int half = 0; half < 2; ++half) {
            const int bb = lane + 32 * half;
            const int x = pp[(bb * NK + kk) * 2 + 0];
            const int y = pp[(bb * NK + kk) * 2 + 1];
            const int cnt = (min(x + HALFW, MAXC) - max(x - HALFW, 0)) *
                            (min(y + HALFW, MAXC) - max(y - HALFW, 0));
            float ssum = 0.f;
#pragma unroll
            for (int xb = 0; xb < 4; ++xb)
                ssum += __ldcg(&g_part[tt][bb][xb][kk]);
            v += ssum * (1.0f / (float)cnt);
        }
#pragma unroll
        for (int off = 16; off > 0; off >>= 1)
            v += __shfl_down_sync(FULLM, v, off);
        if (lane == 0)
            s_fea[g] = v * (1.0f / (float)NB);
    }
    __syncthreads();
    if (tid == 0) {
        float acc2 = 0.f;
#pragma unroll
        for (int kk = 0; kk < NK; ++kk) {
            const float d = s_fea[kk] - 0.999f * s_fea[NK + kk];
            acc2 += d * d;
        }
        out[0] = acc2 * (1.0f / (float)NK);
        g_done = 0;                           // reset for next replay
    }
}

extern "C" void kernel_launch(void* const* d_in, const int* in_sizes, int n_in,
                              void* d_out, int out_size)
{
    const float* f1   = (const float*)d_in[0];
    const float* f2   = (const float*)d_in[1];
    const int*   pre1 = (const int*)d_in[2];
    const int*   pre2 = (const int*)d_in[3];

    fused_kernel<<<dim3(4, NB, 2), 256>>>(f1, f2, pre1, pre2, (float*)d_out);
}

// round 12
// speedup vs baseline: 1.1300x; 1.0991x over previous
#include <cuda_runtime.h>

#define HALFW 6
#define MAXC  63
#define NK    21
#define NB    64
#define NC    256
#define NH    64
#define NW    64
#define HW    (NH * NW)
#define NBLK  512                 // (4, 64, 2)
#define FULLM 0xffffffffu

// Scratch (allocation-free rule: __device__ globals; zero-initialized)
// Transposed for a coalesced finisher: [t][k][xb][b]
__device__ float g_part[2][NK][4][NB];
__device__ int   g_done = 0;            // grid completion (self-resetting)

// ---------------------------------------------------------------------------
// Single fused kernel. grid = (4, 64, 2), block = 256.  (R8 structure, proven
// 84.7us, + producer-side 1/cnt folding + transposed coalesced finisher.)
//  - warp0 builds a 32-bit mask of needed 128B lines (16 rows x 2 half-rows)
//  - threads channel-reduce only needed lines (~93%) -- proven loop shape
//  - fm tile staged in smem; per-block 21 box partials (x 1/cnt) -> g_part
//  - last of 512 blocks sums g_part coalesced + computes MSE
// ---------------------------------------------------------------------------
__global__ void __launch_bounds__(256) fused_kernel(
    const float* __restrict__ f1, const float* __restrict__ f2,
    const int* __restrict__ pre1, const int* __restrict__ pre2,
    float* __restrict__ out)
{
    const int t   = blockIdx.z;
    const int b   = blockIdx.y;
    const int tid = threadIdx.x;
    const int h0  = blockIdx.x * 16;          // this block's row base

    __shared__ __align__(16) float s_fm[16 * NW];  // fm tile (chan-mean), 4KB
    __shared__ int      s_pre[2 * NK];
    __shared__ unsigned s_mask;

    const int* __restrict__ pre = (t == 0) ? pre1 : pre2;
    if (tid < 2 * NK) s_pre[tid] = pre[b * 2 * NK + tid];
    __syncthreads();

    // ---- needed-line mask: line L = (row h0+(L>>1), half (L&1)) ----
    if (tid < 32) {
        const int h  = h0 + (tid >> 1);
        const int c0 = (tid & 1) * 32;        // half-row col base
        bool need = false;
#pragma unroll
        for (int k = 0; k < NK; ++k) {
            const int x = s_pre[2 * k + 0];
            const int y = s_pre[2 * k + 1];
            const int left  = max(x - HALFW, 0);
            const int right = min(x + HALFW, MAXC);   // exclusive
            const int down  = max(y - HALFW, 0);
            const int up    = min(y + HALFW, MAXC);   // exclusive
            need |= (h >= left) & (h < right) & (down < c0 + 32) & (up > c0);
        }
        const unsigned m = __ballot_sync(FULLM, need);
        if (tid == 0) s_mask = m;
    }
    __syncthreads();

    const unsigned mask = s_mask;
    const int nlines    = __popc(mask);
    const int j         = tid >> 3;           // line slot 0..31
    const int f         = tid & 7;            // float4 within 128B line

    // ---- channel reduce over needed lines only (proven loop shape) ----
    if (j < nlines) {
        const int line = __fns(mask, 0, j + 1);   // (j+1)-th set bit
        const int lr = line >> 1;
        const int c4 = (line & 1) * 8 + f;        // float4 col 0..15
        const int hw4 = (h0 + lr) * 16 + c4;

        const float4* __restrict__ f4 =
            reinterpret_cast<const float4*>(t == 0 ? f1 : f2);
        const float4* __restrict__ p = f4 + (size_t)b * NC * (HW / 4) + hw4;

        float4 acc = make_float4(0.f, 0.f, 0.f, 0.f);
#pragma unroll 8
        for (int c = 0; c < NC; ++c) {
            float4 v = p[(size_t)c * (HW / 4)];
            acc.x += v.x; acc.y += v.y; acc.z += v.z; acc.w += v.w;
        }
        const float sc = 1.0f / (float)NC;
        float4 o = make_float4(acc.x * sc, acc.y * sc, acc.z * sc, acc.w * sc);
        *reinterpret_cast<float4*>(&s_fm[lr * NW + c4 * 4]) = o;
    }
    __syncthreads();

    // ---- per-block box partials (x 1/cnt): warp-per-keypoint ----
    const int warp = tid >> 5;
    const int lane = tid & 31;
    for (int k = warp; k < NK; k += 8) {
        const int x = s_pre[2 * k + 0];
        const int y = s_pre[2 * k + 1];
        const int left  = max(x - HALFW, 0);
        const int right = min(x + HALFW, MAXC);
        const int down  = max(y - HALFW, 0);
        const int up    = min(y + HALFW, MAXC);
        const int rl = max(left, h0);
        const int rr = min(right, h0 + 16);
        const int nhl = rr - rl;              // strip-clipped rows, may be <= 0
        const int nw  = up - down;            // 6..12
        const float inv_cnt = 1.0f / (float)((right - left) * nw);  // FULL box

        float s = 0.f;
#pragma unroll
        for (int it = 0; it < 5; ++it) {
            const int idx = lane + 32 * it;   // 0..159
            const int r = idx / 12;           // constant divisor -> mul/shift
            const int c = idx - r * 12;
            if ((idx < 144) && (r < nhl) && (c < nw))
                s += s_fm[(rl - h0 + r) * NW + (down + c)];
        }
#pragma unroll
        for (int off = 16; off > 0; off >>= 1)
            s += __shfl_down_sync(FULLM, s, off);
        if (lane == 0)
            g_part[t][k][blockIdx.x][b] = s * inv_cnt;  // written every call
    }

    // ---- grid completion: last of 512 blocks finishes ----
    __shared__ int s_last;
    if (lane == 0) __threadfence();           // order this warp's g_part store
    __syncthreads();
    if (tid == 0)
        s_last = (atomicAdd(&g_done, 1) == NBLK - 1) ? 1 : 0;
    __syncthreads();
    if (!s_last) return;

    __threadfence();
    __shared__ float s_fea[2 * NK];
    // warp per (t,k); lanes read consecutive b -> fully coalesced
    for (int g = warp; g < 2 * NK; g += 8) {
        const int tt = g / NK;
        const int kk = g - tt * NK;
        float v = 0.f;
#pragma unroll
        for (int xb = 0; xb < 4; ++xb) {
            v += __ldcg(&g_part[tt][kk][xb][lane]);
            v += __ldcg(&g_part[tt][kk][xb][lane + 32]);
        }
#pragma unroll
        for (int off = 16; off > 0; off >>= 1)
            v += __shfl_down_sync(FULLM, v, off);
        if (lane == 0)
            s_fea[g] = v * (1.0f / (float)NB);
    }
    __syncthreads();
    if (tid == 0) {
        float acc2 = 0.f;
#pragma unroll
        for (int kk = 0; kk < NK; ++kk) {
            const float d = s_fea[kk] - 0.999f * s_fea[NK + kk];
            acc2 += d * d;
        }
        out[0] = acc2 * (1.0f / (float)NK);
        g_done = 0;                           // reset for next replay
    }
}

extern "C" void kernel_launch(void* const* d_in, const int* in_sizes, int n_in,
                              void* d_out, int out_size)
{
    const float* f1   = (const float*)d_in[0];
    const float* f2   = (const float*)d_in[1];
    const int*   pre1 = (const int*)d_in[2];
    const int*   pre2 = (const int*)d_in[3];

    fused_kernel<<<dim3(4, NB, 2), 256>>>(f1, f2, pre1, pre2, (float*)d_out);
}